// round 1
// baseline (speedup 1.0000x reference)
#include <cuda_runtime.h>
#include <math.h>

// ReciprocalRankLoss: B=256, P=4, N=1024, D=512, fp32.
// loss = -mean_b( sum_p probs[b,p] / (rank[b,p]+1) ) + 0.3*(1 - mean(pos_sim))
// where probs = softmax(all_sims/0.1) and rank_p = #{sims strictly > pos_sim_p}
// (+ stable-tie rule among the 4 positives). Softmax is monotone => rank over
// sims directly; only positives' ranks are needed => 4 counters per row.

static constexpr int B_   = 256;
static constexpr int P_   = 4;
static constexpr int NNEG = 1024;
static constexpr int D_   = 512;

__device__ float g_err[B_];
__device__ float g_possum[B_];

__global__ void __launch_bounds__(512, 2)
rrl_per_b_kernel(const float* __restrict__ anchor,
                 const float* __restrict__ positives,
                 const float* __restrict__ negatives)
{
    __shared__ float sa[D_];
    __shared__ float s_red[16];
    __shared__ float s_sumexp[16];
    __shared__ int   s_cnt[16][P_];
    __shared__ float s_ps[P_];
    __shared__ float s_na;

    const int b    = blockIdx.x;
    const int tid  = threadIdx.x;
    const int lane = tid & 31;
    const int wid  = tid >> 5;

    // ---- anchor row -> smem, block-reduce squared norm ----
    float av = anchor[(size_t)b * D_ + tid];
    sa[tid] = av;
    float sq = av * av;
    #pragma unroll
    for (int o = 16; o; o >>= 1) sq += __shfl_xor_sync(0xffffffffu, sq, o);
    if (lane == 0) s_red[wid] = sq;
    __syncthreads();
    if (tid < 32) {
        float v = (lane < 16) ? s_red[lane] : 0.0f;
        #pragma unroll
        for (int o = 8; o; o >>= 1) v += __shfl_xor_sync(0xffffffffu, v, o);
        if (lane == 0) s_na = sqrtf(v);
    }
    __syncthreads();
    const float na = s_na;

    const float4* sa4 = reinterpret_cast<const float4*>(sa);
    const float4 a0 = sa4[lane];
    const float4 a1 = sa4[lane + 32];
    const float4 a2 = sa4[lane + 64];
    const float4 a3 = sa4[lane + 96];

    // ---- positive sims: one warp per positive ----
    if (wid < P_) {
        const float4* pr = reinterpret_cast<const float4*>(
            positives + ((size_t)b * P_ + wid) * D_);
        float4 v0 = pr[lane], v1 = pr[lane + 32], v2 = pr[lane + 64], v3 = pr[lane + 96];
        float dot = v0.x*a0.x + v0.y*a0.y + v0.z*a0.z + v0.w*a0.w
                  + v1.x*a1.x + v1.y*a1.y + v1.z*a1.z + v1.w*a1.w
                  + v2.x*a2.x + v2.y*a2.y + v2.z*a2.z + v2.w*a2.w
                  + v3.x*a3.x + v3.y*a3.y + v3.z*a3.z + v3.w*a3.w;
        float nr  = v0.x*v0.x + v0.y*v0.y + v0.z*v0.z + v0.w*v0.w
                  + v1.x*v1.x + v1.y*v1.y + v1.z*v1.z + v1.w*v1.w
                  + v2.x*v2.x + v2.y*v2.y + v2.z*v2.z + v2.w*v2.w
                  + v3.x*v3.x + v3.y*v3.y + v3.z*v3.z + v3.w*v3.w;
        #pragma unroll
        for (int o = 16; o; o >>= 1) {
            dot += __shfl_xor_sync(0xffffffffu, dot, o);
            nr  += __shfl_xor_sync(0xffffffffu, nr, o);
        }
        if (lane == 0) s_ps[wid] = dot / fmaxf(na * sqrtf(nr), 1e-8f);
    }
    __syncthreads();
    const float p0 = s_ps[0], p1 = s_ps[1], p2 = s_ps[2], p3 = s_ps[3];

    // ---- stream 64 negative rows per warp ----
    float sumExp = 0.0f;
    int c0 = 0, c1 = 0, c2 = 0, c3 = 0;
    const int rbase = wid * (NNEG / 16);
    #pragma unroll 2
    for (int r = 0; r < NNEG / 16; ++r) {
        const float4* nr4 = reinterpret_cast<const float4*>(
            negatives + ((size_t)b * NNEG + rbase + r) * D_);
        float4 v0 = nr4[lane], v1 = nr4[lane + 32], v2 = nr4[lane + 64], v3 = nr4[lane + 96];
        float dot = v0.x*a0.x + v0.y*a0.y + v0.z*a0.z + v0.w*a0.w
                  + v1.x*a1.x + v1.y*a1.y + v1.z*a1.z + v1.w*a1.w
                  + v2.x*a2.x + v2.y*a2.y + v2.z*a2.z + v2.w*a2.w
                  + v3.x*a3.x + v3.y*a3.y + v3.z*a3.z + v3.w*a3.w;
        float nrm = v0.x*v0.x + v0.y*v0.y + v0.z*v0.z + v0.w*v0.w
                  + v1.x*v1.x + v1.y*v1.y + v1.z*v1.z + v1.w*v1.w
                  + v2.x*v2.x + v2.y*v2.y + v2.z*v2.z + v2.w*v2.w
                  + v3.x*v3.x + v3.y*v3.y + v3.z*v3.z + v3.w*v3.w;
        #pragma unroll
        for (int o = 16; o; o >>= 1) {
            dot += __shfl_xor_sync(0xffffffffu, dot, o);
            nrm += __shfl_xor_sync(0xffffffffu, nrm, o);
        }
        float sim = dot / fmaxf(na * sqrtf(nrm), 1e-8f);
        if (lane == 0) {
            sumExp += expf(sim * 10.0f);   // 1/TEMPERATURE = 10
            c0 += (sim > p0);
            c1 += (sim > p1);
            c2 += (sim > p2);
            c3 += (sim > p3);
        }
    }
    if (lane == 0) {
        s_sumexp[wid] = sumExp;
        s_cnt[wid][0] = c0; s_cnt[wid][1] = c1;
        s_cnt[wid][2] = c2; s_cnt[wid][3] = c3;
    }
    __syncthreads();

    // ---- finalize this batch row (deterministic serial reduce over 16 warps) ----
    if (tid == 0) {
        float Z = 0.0f;
        int cc[P_] = {0, 0, 0, 0};
        for (int w = 0; w < 16; ++w) {
            Z += s_sumexp[w];
            cc[0] += s_cnt[w][0]; cc[1] += s_cnt[w][1];
            cc[2] += s_cnt[w][2]; cc[3] += s_cnt[w][3];
        }
        float ps[P_] = {p0, p1, p2, p3};
        float ev[P_];
        #pragma unroll
        for (int p = 0; p < P_; ++p) ev[p] = expf(ps[p] * 10.0f);
        Z += ev[0] + ev[1] + ev[2] + ev[3];
        float err = 0.0f;
        #pragma unroll
        for (int p = 0; p < P_; ++p) {
            int rank = cc[p];
            #pragma unroll
            for (int q = 0; q < P_; ++q) {
                if (q == p) continue;
                // stable argsort of -probs: q outranks p if strictly larger sim,
                // or equal sim with smaller index.
                if (ps[q] > ps[p] || (q < p && ps[q] == ps[p])) rank++;
            }
            err += (ev[p] / Z) * (1.0f / (float)(rank + 1));
        }
        g_err[b]    = err;
        g_possum[b] = p0 + p1 + p2 + p3;
    }
}

__global__ void __launch_bounds__(256)
rrl_finalize_kernel(float* __restrict__ out)
{
    __shared__ float s_e[8];
    __shared__ float s_s[8];
    const int tid  = threadIdx.x;
    const int lane = tid & 31;
    const int wid  = tid >> 5;

    float e = g_err[tid];
    float s = g_possum[tid];
    #pragma unroll
    for (int o = 16; o; o >>= 1) {
        e += __shfl_xor_sync(0xffffffffu, e, o);
        s += __shfl_xor_sync(0xffffffffu, s, o);
    }
    if (lane == 0) { s_e[wid] = e; s_s[wid] = s; }
    __syncthreads();
    if (tid == 0) {
        float esum = 0.0f, ssum = 0.0f;
        for (int w = 0; w < 8; ++w) { esum += s_e[w]; ssum += s_s[w]; }
        float mean_err = esum / (float)B_;
        float mean_pos = ssum / (float)(B_ * P_);
        out[0] = -mean_err + 0.3f * (1.0f - mean_pos);
    }
}

extern "C" void kernel_launch(void* const* d_in, const int* in_sizes, int n_in,
                              void* d_out, int out_size)
{
    const float* anchor    = (const float*)d_in[0];
    const float* positives = (const float*)d_in[1];
    const float* negatives = (const float*)d_in[2];
    float* out = (float*)d_out;

    rrl_per_b_kernel<<<B_, 512>>>(anchor, positives, negatives);
    rrl_finalize_kernel<<<1, 256>>>(out);
}